// round 15
// baseline (speedup 1.0000x reference)
#include <cuda_runtime.h>
#include <cuda_fp16.h>
#include <cstdint>

// ============================================================
// BinaryMLP fused kernel (sm_103 virtual arch — portable mma.sync).
// R14: exact R10 instruction stream (the 194.7us best; R11's manual
// double-buffering reverted) with NWARP 12->13. Fits by XSTRIDE
// 800->784 (tail cols 196..199 handled by predication instead of a
// zero pad) and trimming the b4 smem pad. cp.async x staging,
// grouped B loads (1 LDS.128 per 4 MMAs), sign-byte weights + PRMT,
// fp16 single-pass, zero barriers in steady state.
// ============================================================

#define DIN   196
#define HID   128
#define DOUT  10
#define NWARP 13
#define CTA_THREADS (NWARP * 32)
#define XSTRIDE 784                      // bytes per staged row (196 floats, 16B-mult)
#define XBUF_PER_WARP (16 * XSTRIDE)     // 12544 B

// ---- smem layout ----
#define SM_W1S  0                        // 13*4*512 = 26624
#define SM_W2S  (SM_W1S + 13*4*512)
#define SM_W3S  (SM_W2S + 8*4*512)
#define SM_W4HF (SM_W3S + 8*4*512)       // [8][16]*32 = 4096
#define SM_W4LF (SM_W4HF + 8*16*32)
#define SM_B1   (SM_W4LF + 8*16*32)
#define SM_B2   (SM_B1 + 512)
#define SM_B3   (SM_B2 + 512)
#define SM_B4   (SM_B3 + 512)
#define SM_XBUF (SM_B4 + 64)             // 13 * 12544 = 163072
#define SM_TOTAL (SM_XBUF + NWARP * XBUF_PER_WARP)   // 232256 <= 232448

__device__ __forceinline__ int frag_off(int k) {
    return ((k & 7) >> 1) * 8 + ((k >> 3) & 1) * 4 + (k & 1) * 2;
}
__device__ __forceinline__ int sgn_addr(int n, int k) {
    int kk = k >> 4, nb = n >> 3, ng = nb >> 2, j = nb & 3;
    return ((kk * 4 + ng) << 9) + (((n & 7) * 4 + ((k & 7) >> 1)) << 4)
         + (j << 2) + (((k >> 3) & 1) << 1) + (k & 1);
}

__device__ __forceinline__ void mma16816(float* d, const uint32_t* a, const uint32_t* b) {
    asm volatile(
        "mma.sync.aligned.m16n8k16.row.col.f32.f16.f16.f32 "
        "{%0,%1,%2,%3},{%4,%5,%6,%7},{%8,%9},{%0,%1,%2,%3};"
        : "+f"(d[0]), "+f"(d[1]), "+f"(d[2]), "+f"(d[3])
        : "r"(a[0]), "r"(a[1]), "r"(a[2]), "r"(a[3]), "r"(b[0]), "r"(b[1]));
}

__device__ __forceinline__ uint32_t h2pack(float a, float b) {
    __half2 h = __floats2half2_rn(a, b);
    return *reinterpret_cast<uint32_t*>(&h);
}

#define CP_ASYNC16(dst_u32, gptr) \
    asm volatile("cp.async.cg.shared.global [%0], [%1], 16;" :: "r"(dst_u32), "l"(gptr) : "memory")
#define CP_COMMIT() asm volatile("cp.async.commit_group;" ::: "memory")
#define CP_WAIT0()  asm volatile("cp.async.wait_group 0;" ::: "memory")

// D -> +bias, ReLU, fp16 pack -> A fragments for next layer
__device__ __forceinline__ void epilogue_hidden(
    const float D[16][4], const float* bias, int q, uint32_t Ah[8][4])
{
    #pragma unroll
    for (int kk = 0; kk < 8; kk++) {
        const float* bp = bias + 16 * kk + q * 2;
        float2 b0 = *(const float2*)bp;
        float2 b1 = *(const float2*)(bp + 8);
        int f0 = 2 * kk, f1 = f0 + 1;
        Ah[kk][0] = h2pack(fmaxf(D[f0][0] + b0.x, 0.f), fmaxf(D[f0][1] + b0.y, 0.f));
        Ah[kk][1] = h2pack(fmaxf(D[f0][2] + b0.x, 0.f), fmaxf(D[f0][3] + b0.y, 0.f));
        Ah[kk][2] = h2pack(fmaxf(D[f1][0] + b1.x, 0.f), fmaxf(D[f1][1] + b1.y, 0.f));
        Ah[kk][3] = h2pack(fmaxf(D[f1][2] + b1.x, 0.f), fmaxf(D[f1][3] + b1.y, 0.f));
    }
}

__global__ void __launch_bounds__(CTA_THREADS, 1) bmlp_kernel(
    const float* __restrict__ x,
    const float* __restrict__ W1, const float* __restrict__ b1,
    const float* __restrict__ W2, const float* __restrict__ b2,
    const float* __restrict__ W3, const float* __restrict__ b3,
    const float* __restrict__ W4, const float* __restrict__ b4,
    float* __restrict__ out, int n_chunks)
{
    extern __shared__ char smem[];
    const int tid = threadIdx.x;
    const int lane = tid & 31;
    const int warp = tid >> 5;
    const int r = lane >> 2;
    const int q = lane & 3;

    // ---------------- prologue: weights -> smem ----------------
    for (int i = tid; i < HID * 208; i += CTA_THREADS) {
        int n = i / 208, k = i - n * 208;
        unsigned char s = 0;
        if (k < DIN) {
            float w = W1[n * DIN + k];
            s = (w > 0.f) ? 0x3Cu : ((w < 0.f) ? 0xBCu : 0u);
        }
        smem[SM_W1S + sgn_addr(n, k)] = s;
    }
    for (int i = tid; i < HID * HID; i += CTA_THREADS) {
        int n = i >> 7, k = i & 127;
        float w2 = W2[i], w3 = W3[i];
        unsigned char s2 = (w2 > 0.f) ? 0x3Cu : ((w2 < 0.f) ? 0xBCu : 0u);
        unsigned char s3 = (w3 > 0.f) ? 0x3Cu : ((w3 < 0.f) ? 0xBCu : 0u);
        int a = sgn_addr(n, k);
        smem[SM_W2S + a] = s2;
        smem[SM_W3S + a] = s3;
    }
    for (int i = tid; i < 16 * HID; i += CTA_THREADS) {
        int n = i >> 7, k = i & 127;
        float w = (n < DOUT) ? W4[n * HID + k] : 0.f;
        __half h = __float2half_rn(w);
        __half l = __float2half_rn(w - __half2float(h));
        int ofs = ((k >> 4) * 16 + n) * 32 + frag_off(k);
        *(unsigned short*)(smem + SM_W4HF + ofs) = __half_as_ushort(h);
        *(unsigned short*)(smem + SM_W4LF + ofs) = __half_as_ushort(l);
    }
    if (tid < HID) {
        ((float*)(smem + SM_B1))[tid] = b1[tid];
        ((float*)(smem + SM_B2))[tid] = b2[tid];
        ((float*)(smem + SM_B3))[tid] = b3[tid];
    }
    if (tid < 16) ((float*)(smem + SM_B4))[tid] = (tid < DOUT) ? b4[tid] : 0.f;
    __syncthreads();
    // Zero barriers after this point: warps fully independent.

    char* xbuf = smem + SM_XBUF + warp * XBUF_PER_WARP;
    const float* b1s = (const float*)(smem + SM_B1);
    const float* b2s = (const float*)(smem + SM_B2);
    const float* b3s = (const float*)(smem + SM_B3);
    const float* b4s = (const float*)(smem + SM_B4);
    const char* w1p = smem + SM_W1S + lane * 16;
    const char* w2p = smem + SM_W2S + lane * 16;
    const char* w3p = smem + SM_W3S + lane * 16;

    const int wstride = gridDim.x * NWARP;
    const int c_first = blockIdx.x * NWARP + warp;

    // ---- prime the pipeline: prefetch the first chunk ----
    if (c_first < n_chunks) {
        const char* gbase = (const char*)(x + (size_t)c_first * 16 * DIN);
        for (int u = lane; u < 784; u += 32) {
            int row = u / 49, off = (u - row * 49) * 16;
            uint32_t dst = (uint32_t)__cvta_generic_to_shared(xbuf + row * XSTRIDE + off);
            CP_ASYNC16(dst, gbase + row * 784 + off);
        }
    }
    CP_COMMIT();

    for (int c = c_first; c < n_chunks; c += wstride) {
        CP_WAIT0();     // x for chunk c is resident in xbuf

        float D[16][4];
        #pragma unroll
        for (int f = 0; f < 16; f++)
            #pragma unroll
            for (int j = 0; j < 4; j++) D[f][j] = 0.f;

        // ---- layer 1: A from staged x (rows r, r+8), 13 k-steps ----
        #pragma unroll
        for (int kk = 0; kk < 13; kk++) {
            int c0 = kk * 16 + q * 2;
            uint32_t a[4];
            if (kk < 12) {
                float2 p0 = *(const float2*)(xbuf + r * XSTRIDE + c0 * 4);
                float2 p1 = *(const float2*)(xbuf + (r + 8) * XSTRIDE + c0 * 4);
                a[0] = h2pack(p0.x, p0.y);
                a[1] = h2pack(p1.x, p1.y);
                int c1 = c0 + 8;
                float2 p2 = *(const float2*)(xbuf + r * XSTRIDE + c1 * 4);
                float2 p3 = *(const float2*)(xbuf + (r + 8) * XSTRIDE + c1 * 4);
                a[2] = h2pack(p2.x, p2.y);
                a[3] = h2pack(p3.x, p3.y);
            } else {
                // tail k-step: cols 192..195 real (q<2), 196..207 zero
                float2 z = make_float2(0.f, 0.f);
                float2 p0 = (c0 < DIN) ? *(const float2*)(xbuf + r * XSTRIDE + c0 * 4) : z;
                float2 p1 = (c0 < DIN) ? *(const float2*)(xbuf + (r + 8) * XSTRIDE + c0 * 4) : z;
                a[0] = h2pack(p0.x, p0.y);
                a[1] = h2pack(p1.x, p1.y);
                a[2] = 0u; a[3] = 0u;
            }
            #pragma unroll
            for (int ng = 0; ng < 4; ng++) {
                uint4 w = *(const uint4*)(w1p + (((kk * 4 + ng) << 9)));
                uint32_t bw0[2] = { __byte_perm(w.x, 0, 0x1404), __byte_perm(w.x, 0, 0x3424) };
                uint32_t bw1[2] = { __byte_perm(w.y, 0, 0x1404), __byte_perm(w.y, 0, 0x3424) };
                uint32_t bw2[2] = { __byte_perm(w.z, 0, 0x1404), __byte_perm(w.z, 0, 0x3424) };
                uint32_t bw3[2] = { __byte_perm(w.w, 0, 0x1404), __byte_perm(w.w, 0, 0x3424) };
                mma16816(D[ng * 4 + 0], a, bw0);
                mma16816(D[ng * 4 + 1], a, bw1);
                mma16816(D[ng * 4 + 2], a, bw2);
                mma16816(D[ng * 4 + 3], a, bw3);
            }
        }

        // ---- prefetch next chunk's x (all layer-1 xbuf reads issued) ----
        {
            int cn = c + wstride;
            if (cn < n_chunks) {
                const char* gbase = (const char*)(x + (size_t)cn * 16 * DIN);
                for (int u = lane; u < 784; u += 32) {
                    int row = u / 49, off = (u - row * 49) * 16;
                    uint32_t dst = (uint32_t)__cvta_generic_to_shared(xbuf + row * XSTRIDE + off);
                    CP_ASYNC16(dst, gbase + row * 784 + off);
                }
            }
            CP_COMMIT();
        }

        uint32_t Ah[8][4];
        epilogue_hidden(D, b1s, q, Ah);

        // ---- layers 2 and 3 ----
        #pragma unroll
        for (int L = 0; L < 2; L++) {
            const char* Ws = (L == 0) ? w2p : w3p;
            const float* bs = (L == 0) ? b2s : b3s;
            #pragma unroll
            for (int f = 0; f < 16; f++)
                #pragma unroll
                for (int j = 0; j < 4; j++) D[f][j] = 0.f;
            #pragma unroll
            for (int kk = 0; kk < 8; kk++) {
                #pragma unroll
                for (int ng = 0; ng < 4; ng++) {
                    uint4 w = *(const uint4*)(Ws + (((kk * 4 + ng) << 9)));
                    uint32_t bw0[2] = { __byte_perm(w.x, 0, 0x1404), __byte_perm(w.x, 0, 0x3424) };
                    uint32_t bw1[2] = { __byte_perm(w.y, 0, 0x1404), __byte_perm(w.y, 0, 0x3424) };
                    uint32_t bw2[2] = { __byte_perm(w.z, 0, 0x1404), __byte_perm(w.z, 0, 0x3424) };
                    uint32_t bw3[2] = { __byte_perm(w.w, 0, 0x1404), __byte_perm(w.w, 0, 0x3424) };
                    mma16816(D[ng * 4 + 0], Ah[kk], bw0);
                    mma16816(D[ng * 4 + 1], Ah[kk], bw1);
                    mma16816(D[ng * 4 + 2], Ah[kk], bw2);
                    mma16816(D[ng * 4 + 3], Ah[kk], bw3);
                }
            }
            epilogue_hidden(D, bs, q, Ah);
        }

        // ---- layer 4 (head; W4 = hi + lo fp16) ----
        float D4[2][4];
        #pragma unroll
        for (int f = 0; f < 2; f++)
            #pragma unroll
            for (int j = 0; j < 4; j++) D4[f][j] = 0.f;
        #pragma unroll
        for (int kk = 0; kk < 8; kk++) {
            #pragma unroll
            for (int n = 0; n < 2; n++) {
                int ofs = ((kk * 16 + n * 8 + r) << 5) + q * 8;
                uint2 bhw = *(const uint2*)(smem + SM_W4HF + ofs);
                uint2 blw = *(const uint2*)(smem + SM_W4LF + ofs);
                uint32_t bh[2] = { bhw.x, bhw.y };
                uint32_t bl[2] = { blw.x, blw.y };
                mma16816(D4[n], Ah[kk], bh);
                mma16816(D4[n], Ah[kk], bl);
            }
        }

        // ---- output ----
        {
            const size_t row0 = (size_t)c * 16 + r;
            float* o0 = out + row0 * DOUT;
            float* o8 = o0 + (size_t)8 * DOUT;
            int cc = q * 2;
            float2 bb = *(const float2*)(b4s + cc);
            *(float2*)(o0 + cc) = make_float2(D4[0][0] + bb.x, D4[0][1] + bb.y);
            *(float2*)(o8 + cc) = make_float2(D4[0][2] + bb.x, D4[0][3] + bb.y);
            if (q == 0) {
                float2 b8 = *(const float2*)(b4s + 8);
                *(float2*)(o0 + 8) = make_float2(D4[1][0] + b8.x, D4[1][1] + b8.y);
                *(float2*)(o8 + 8) = make_float2(D4[1][2] + b8.x, D4[1][3] + b8.y);
            }
        }
    }
}

extern "C" void kernel_launch(void* const* d_in, const int* in_sizes, int n_in,
                              void* d_out, int out_size) {
    const float* x  = (const float*)d_in[0];
    const float* W1 = (const float*)d_in[1];
    const float* b1 = (const float*)d_in[2];
    const float* W2 = (const float*)d_in[3];
    const float* b2 = (const float*)d_in[4];
    const float* W3 = (const float*)d_in[5];
    const float* b3 = (const float*)d_in[6];
    const float* W4 = (const float*)d_in[7];
    const float* b4 = (const float*)d_in[8];
    float* out = (float*)d_out;

    int B = in_sizes[0] / DIN;
    int n_chunks = B / 16;

    static int configured = 0;
    if (!configured) {
        cudaFuncSetAttribute(bmlp_kernel, cudaFuncAttributeMaxDynamicSharedMemorySize, SM_TOTAL);
        configured = 1;
    }

    int grid = 152;
    int max_grid = (n_chunks + NWARP - 1) / NWARP;
    if (grid > max_grid) grid = max_grid;
    bmlp_kernel<<<grid, CTA_THREADS, SM_TOTAL>>>(x, W1, b1, W2, b2, W3, b3, W4, b4, out, n_chunks);
}

// round 16
// speedup vs baseline: 1.1301x; 1.1301x over previous
#include <cuda_runtime.h>
#include <cuda_fp16.h>
#include <cstdint>

// ============================================================
// BinaryMLP fused kernel (sm_103 virtual arch — portable mma.sync).
// R16: weights PRE-EXPANDED to fp16 MMA fragments in smem (prologue
// does the binarize+expand once) -> mainloop B path is pure LDS.128,
// ZERO PRMT (R10 spent ~40% of issue slots on PRMT+plumbing).
// 1 LDS.128 feeds 2 MMAs. 8 warps/CTA (smem-limited), cp.async x
// staging (R10), fp16 single-pass, zero barriers in steady state.
// ============================================================

#define DIN   196
#define HID   128
#define DOUT  10
#define NWARP 8
#define CTA_THREADS (NWARP * 32)
#define XSTRIDE 800                      // bytes per staged row (200 floats)
#define XBUF_PER_WARP (16 * XSTRIDE)     // 12800 B

// ---- smem layout (expanded fp16 fragments) ----
// Block per (kstep, n-pair of 2 n-blocks): 512 B. Lane l reads uint4 at
// l*16: {b0,b1} for n-block 2p (w.x,w.y) and 2p+1 (w.z,w.w).
#define SM_W1F  0                        // 13*8*512 = 53248
#define SM_W2F  (SM_W1F + 13*8*512)      // 8*8*512 = 32768
#define SM_W3F  (SM_W2F + 8*8*512)
#define SM_W4HF (SM_W3F + 8*8*512)       // [8][16]*32 = 4096
#define SM_W4LF (SM_W4HF + 4096)
#define SM_B1   (SM_W4LF + 4096)
#define SM_B2   (SM_B1 + 512)
#define SM_B3   (SM_B2 + 512)
#define SM_B4   (SM_B3 + 512)
#define SM_XBUF (SM_B4 + 64)             // base 128576
#define SM_TOTAL (SM_XBUF + NWARP * XBUF_PER_WARP)   // 230976 <= 232448

// fp16-frag byte offset within a 32B block (W4 head, unchanged)
__device__ __forceinline__ int frag_off(int k) {
    return ((k & 7) >> 1) * 8 + ((k >> 3) & 1) * 4 + (k & 1) * 2;
}
// expanded-fragment address for weight (n, k)
__device__ __forceinline__ int exp_addr(int n, int k) {
    int kk = k >> 4, p = n >> 4, sub = (n >> 3) & 1;
    int ln = ((n & 7) << 2) + ((k & 7) >> 1);
    int b  = (k >> 3) & 1;
    return ((kk * 8 + p) << 9) + (ln << 4) + (sub << 3) + (b << 2) + ((k & 1) << 1);
}

__device__ __forceinline__ void mma16816(float* d, const uint32_t* a, const uint32_t* b) {
    asm volatile(
        "mma.sync.aligned.m16n8k16.row.col.f32.f16.f16.f32 "
        "{%0,%1,%2,%3},{%4,%5,%6,%7},{%8,%9},{%0,%1,%2,%3};"
        : "+f"(d[0]), "+f"(d[1]), "+f"(d[2]), "+f"(d[3])
        : "r"(a[0]), "r"(a[1]), "r"(a[2]), "r"(a[3]), "r"(b[0]), "r"(b[1]));
}

__device__ __forceinline__ uint32_t h2pack(float a, float b) {
    __half2 h = __floats2half2_rn(a, b);
    return *reinterpret_cast<uint32_t*>(&h);
}

#define CP_ASYNC16(dst_u32, gptr) \
    asm volatile("cp.async.cg.shared.global [%0], [%1], 16;" :: "r"(dst_u32), "l"(gptr) : "memory")
#define CP_COMMIT() asm volatile("cp.async.commit_group;" ::: "memory")
#define CP_WAIT0()  asm volatile("cp.async.wait_group 0;" ::: "memory")

// D -> +bias, ReLU, fp16 pack -> A fragments for next layer
__device__ __forceinline__ void epilogue_hidden(
    const float D[16][4], const float* bias, int q, uint32_t Ah[8][4])
{
    #pragma unroll
    for (int kk = 0; kk < 8; kk++) {
        const float* bp = bias + 16 * kk + q * 2;
        float2 b0 = *(const float2*)bp;
        float2 b1 = *(const float2*)(bp + 8);
        int f0 = 2 * kk, f1 = f0 + 1;
        Ah[kk][0] = h2pack(fmaxf(D[f0][0] + b0.x, 0.f), fmaxf(D[f0][1] + b0.y, 0.f));
        Ah[kk][1] = h2pack(fmaxf(D[f0][2] + b0.x, 0.f), fmaxf(D[f0][3] + b0.y, 0.f));
        Ah[kk][2] = h2pack(fmaxf(D[f1][0] + b1.x, 0.f), fmaxf(D[f1][1] + b1.y, 0.f));
        Ah[kk][3] = h2pack(fmaxf(D[f1][2] + b1.x, 0.f), fmaxf(D[f1][3] + b1.y, 0.f));
    }
}

__global__ void __launch_bounds__(CTA_THREADS, 1) bmlp_kernel(
    const float* __restrict__ x,
    const float* __restrict__ W1, const float* __restrict__ b1,
    const float* __restrict__ W2, const float* __restrict__ b2,
    const float* __restrict__ W3, const float* __restrict__ b3,
    const float* __restrict__ W4, const float* __restrict__ b4,
    float* __restrict__ out, int n_chunks)
{
    extern __shared__ char smem[];
    const int tid = threadIdx.x;
    const int lane = tid & 31;
    const int warp = tid >> 5;
    const int r = lane >> 2;
    const int q = lane & 3;

    // ---------------- prologue: binarize + expand weights -> smem ----------------
    const unsigned short PF = 0x3C00u;   // fp16 +1
    const unsigned short NF = 0xBC00u;   // fp16 -1

    for (int i = tid; i < HID * 208; i += CTA_THREADS) {
        int n = i / 208, k = i - n * 208;
        unsigned short s = 0;
        if (k < DIN) {
            float w = W1[n * DIN + k];
            s = (w > 0.f) ? PF : ((w < 0.f) ? NF : (unsigned short)0);
        }
        *(unsigned short*)(smem + SM_W1F + exp_addr(n, k)) = s;
    }
    for (int i = tid; i < HID * HID; i += CTA_THREADS) {
        int n = i >> 7, k = i & 127;
        float w2 = W2[i], w3 = W3[i];
        unsigned short s2 = (w2 > 0.f) ? PF : ((w2 < 0.f) ? NF : (unsigned short)0);
        unsigned short s3 = (w3 > 0.f) ? PF : ((w3 < 0.f) ? NF : (unsigned short)0);
        int a = exp_addr(n, k);
        *(unsigned short*)(smem + SM_W2F + a) = s2;
        *(unsigned short*)(smem + SM_W3F + a) = s3;
    }
    for (int i = tid; i < 16 * HID; i += CTA_THREADS) {
        int n = i >> 7, k = i & 127;
        float w = (n < DOUT) ? W4[n * HID + k] : 0.f;
        __half h = __float2half_rn(w);
        __half l = __float2half_rn(w - __half2float(h));
        int ofs = ((k >> 4) * 16 + n) * 32 + frag_off(k);
        *(unsigned short*)(smem + SM_W4HF + ofs) = __half_as_ushort(h);
        *(unsigned short*)(smem + SM_W4LF + ofs) = __half_as_ushort(l);
    }
    if (tid < HID) {
        ((float*)(smem + SM_B1))[tid] = b1[tid];
        ((float*)(smem + SM_B2))[tid] = b2[tid];
        ((float*)(smem + SM_B3))[tid] = b3[tid];
    }
    if (tid < 16) ((float*)(smem + SM_B4))[tid] = (tid < DOUT) ? b4[tid] : 0.f;

    // zero per-row pad (cols 196..199) of this warp's x stage
    char* xbuf = smem + SM_XBUF + warp * XBUF_PER_WARP;
    if (lane < 16)
        *(uint4*)(xbuf + lane * XSTRIDE + 784) = make_uint4(0, 0, 0, 0);
    __syncthreads();
    // Zero barriers after this point: warps fully independent.

    const float* b1s = (const float*)(smem + SM_B1);
    const float* b2s = (const float*)(smem + SM_B2);
    const float* b3s = (const float*)(smem + SM_B3);
    const float* b4s = (const float*)(smem + SM_B4);
    const char* w1p = smem + SM_W1F + lane * 16;
    const char* w2p = smem + SM_W2F + lane * 16;
    const char* w3p = smem + SM_W3F + lane * 16;

    const int wstride = gridDim.x * NWARP;
    const int c_first = blockIdx.x * NWARP + warp;

    // ---- prime the pipeline: prefetch the first chunk ----
    if (c_first < n_chunks) {
        const char* gbase = (const char*)(x + (size_t)c_first * 16 * DIN);
        for (int u = lane; u < 784; u += 32) {
            int row = u / 49, off = (u - row * 49) * 16;
            uint32_t dst = (uint32_t)__cvta_generic_to_shared(xbuf + row * XSTRIDE + off);
            CP_ASYNC16(dst, gbase + row * 784 + off);
        }
    }
    CP_COMMIT();

    for (int c = c_first; c < n_chunks; c += wstride) {
        CP_WAIT0();     // x for chunk c is resident in xbuf

        float D[16][4];
        #pragma unroll
        for (int f = 0; f < 16; f++)
            #pragma unroll
            for (int j = 0; j < 4; j++) D[f][j] = 0.f;

        // ---- layer 1: A from staged x, 13 k-steps, B pure LDS.128 ----
        #pragma unroll
        for (int kk = 0; kk < 13; kk++) {
            int c0 = kk * 16 + q * 2;           // <= 198: pad cols hold zeros
            uint32_t a[4];
            float2 p0 = *(const float2*)(xbuf + r * XSTRIDE + c0 * 4);
            float2 p1 = *(const float2*)(xbuf + (r + 8) * XSTRIDE + c0 * 4);
            a[0] = h2pack(p0.x, p0.y);
            a[1] = h2pack(p1.x, p1.y);
            if (kk < 12) {
                int c1 = c0 + 8;
                float2 p2 = *(const float2*)(xbuf + r * XSTRIDE + c1 * 4);
                float2 p3 = *(const float2*)(xbuf + (r + 8) * XSTRIDE + c1 * 4);
                a[2] = h2pack(p2.x, p2.y);
                a[3] = h2pack(p3.x, p3.y);
            } else {
                a[2] = 0u; a[3] = 0u;           // cols 200..207: pure pad
            }
            #pragma unroll
            for (int p = 0; p < 8; p++) {
                uint4 w = *(const uint4*)(w1p + (((kk * 8 + p) << 9)));
                uint32_t bA[2] = { w.x, w.y };
                uint32_t bB[2] = { w.z, w.w };
                mma16816(D[2 * p],     a, bA);
                mma16816(D[2 * p + 1], a, bB);
            }
        }

        // ---- prefetch next chunk's x ----
        {
            int cn = c + wstride;
            if (cn < n_chunks) {
                const char* gbase = (const char*)(x + (size_t)cn * 16 * DIN);
                for (int u = lane; u < 784; u += 32) {
                    int row = u / 49, off = (u - row * 49) * 16;
                    uint32_t dst = (uint32_t)__cvta_generic_to_shared(xbuf + row * XSTRIDE + off);
                    CP_ASYNC16(dst, gbase + row * 784 + off);
                }
            }
            CP_COMMIT();
        }

        uint32_t Ah[8][4];
        epilogue_hidden(D, b1s, q, Ah);

        // ---- layers 2 and 3 ----
        #pragma unroll
        for (int L = 0; L < 2; L++) {
            const char* Ws = (L == 0) ? w2p : w3p;
            const float* bs = (L == 0) ? b2s : b3s;
            #pragma unroll
            for (int f = 0; f < 16; f++)
                #pragma unroll
                for (int j = 0; j < 4; j++) D[f][j] = 0.f;
            #pragma unroll
            for (int kk = 0; kk < 8; kk++) {
                #pragma unroll
                for (int p = 0; p < 8; p++) {
                    uint4 w = *(const uint4*)(Ws + (((kk * 8 + p) << 9)));
                    uint32_t bA[2] = { w.x, w.y };
                    uint32_t bB[2] = { w.z, w.w };
                    mma16816(D[2 * p],     Ah[kk], bA);
                    mma16816(D[2 * p + 1], Ah[kk], bB);
                }
            }
            epilogue_hidden(D, bs, q, Ah);
        }

        // ---- layer 4 (head; W4 = hi + lo fp16) ----
        float D4[2][4];
        #pragma unroll
        for (int f = 0; f < 2; f++)
            #pragma unroll
            for (int j = 0; j < 4; j++) D4[f][j] = 0.f;
        #pragma unroll
        for (int kk = 0; kk < 8; kk++) {
            #pragma unroll
            for (int n = 0; n < 2; n++) {
                int ofs = ((kk * 16 + n * 8 + r) << 5) + q * 8;
                uint2 bhw = *(const uint2*)(smem + SM_W4HF + ofs);
                uint2 blw = *(const uint2*)(smem + SM_W4LF + ofs);
                uint32_t bh[2] = { bhw.x, bhw.y };
                uint32_t bl[2] = { blw.x, blw.y };
                mma16816(D4[n], Ah[kk], bh);
                mma16816(D4[n], Ah[kk], bl);
            }
        }

        // ---- output ----
        {
            const size_t row0 = (size_t)c * 16 + r;
            float* o0 = out + row0 * DOUT;
            float* o8 = o0 + (size_t)8 * DOUT;
            int cc = q * 2;
            float2 bb = *(const float2*)(b4s + cc);
            *(float2*)(o0 + cc) = make_float2(D4[0][0] + bb.x, D4[0][1] + bb.y);
            *(float2*)(o8 + cc) = make_float2(D4[0][2] + bb.x, D4[0][3] + bb.y);
            if (q == 0) {
                float2 b8 = *(const float2*)(b4s + 8);
                *(float2*)(o0 + 8) = make_float2(D4[1][0] + b8.x, D4[1][1] + b8.y);
                *(float2*)(o8 + 8) = make_float2(D4[1][2] + b8.x, D4[1][3] + b8.y);
            }
        }
    }
}

extern "C" void kernel_launch(void* const* d_in, const int* in_sizes, int n_in,
                              void* d_out, int out_size) {
    const float* x  = (const float*)d_in[0];
    const float* W1 = (const float*)d_in[1];
    const float* b1 = (const float*)d_in[2];
    const float* W2 = (const float*)d_in[3];
    const float* b2 = (const float*)d_in[4];
    const float* W3 = (const float*)d_in[5];
    const float* b3 = (const float*)d_in[6];
    const float* W4 = (const float*)d_in[7];
    const float* b4 = (const float*)d_in[8];
    float* out = (float*)d_out;

    int B = in_sizes[0] / DIN;
    int n_chunks = B / 16;

    static int configured = 0;
    if (!configured) {
        cudaFuncSetAttribute(bmlp_kernel, cudaFuncAttributeMaxDynamicSharedMemorySize, SM_TOTAL);
        configured = 1;
    }

    int grid = 152;
    int max_grid = (n_chunks + NWARP - 1) / NWARP;
    if (grid > max_grid) grid = max_grid;
    bmlp_kernel<<<grid, CTA_THREADS, SM_TOTAL>>>(x, W1, b1, W2, b2, W3, b3, W4, b4, out, n_chunks);
}